// round 1
// baseline (speedup 1.0000x reference)
#include <cuda_runtime.h>

#define NN 100000
#define NE 1600000
#define DC 128
#define NL 3

// ---------------- scratch (device globals; no allocations allowed) ----------
__device__ float g_z [(size_t)NN * DC];   // aggregated input to GEMM1
__device__ float g_t1[(size_t)NN * DC];   // GEMM1 output (pre-BN1)
__device__ float g_t2[(size_t)NN * DC];   // GEMM2 output (pre-BN2)
__device__ float g_stats[2 * DC];         // per-channel sum / sumsq
__device__ float g_aff [2 * DC];          // per-channel affine: a[c], c[c]

// ---------------- tiny utility kernels --------------------------------------
__global__ void k_zero_stats() { g_stats[threadIdx.x] = 0.f; }

// out[i] = (AFF ? relu?(a*in+c) : in)   elementwise over N*D
template<bool AFF>
__global__ void k_affine(const float* __restrict__ in, float* __restrict__ out, int relu)
{
    int i = blockIdx.x * blockDim.x + threadIdx.x;
    const int n4 = NN * DC / 4;
    if (i >= n4) return;
    float4 v = __ldg((const float4*)in + i);
    if (AFF) {
        int c4 = i & (DC / 4 - 1);
        float4 a = *((const float4*)g_aff + c4);
        float4 c = *((const float4*)g_aff + DC / 4 + c4);
        v.x = fmaf(a.x, v.x, c.x);
        v.y = fmaf(a.y, v.y, c.y);
        v.z = fmaf(a.z, v.z, c.z);
        v.w = fmaf(a.w, v.w, c.w);
        if (relu) {
            v.x = fmaxf(v.x, 0.f); v.y = fmaxf(v.y, 0.f);
            v.z = fmaxf(v.z, 0.f); v.w = fmaxf(v.w, 0.f);
        }
    }
    ((float4*)out)[i] = v;
}

// ---------------- edge scatter-add: g_z[dst] += f(h[src]) -------------------
// one warp per edge; lane covers 4 channels; vector red.global.add.v4.f32
template<bool AFF>
__global__ void k_scatter(const float* __restrict__ h, const int* __restrict__ ei, int relu)
{
    int gt = blockIdx.x * blockDim.x + threadIdx.x;
    int e = gt >> 5;
    int lane = gt & 31;
    if (e >= NE) return;
    int src = __ldg(ei + e);
    int dst = __ldg(ei + NE + e);
    float4 v = __ldg((const float4*)(h + (size_t)src * DC) + lane);
    if (AFF) {
        float4 a = *((const float4*)g_aff + lane);
        float4 c = *((const float4*)g_aff + DC / 4 + lane);
        v.x = fmaf(a.x, v.x, c.x);
        v.y = fmaf(a.y, v.y, c.y);
        v.z = fmaf(a.z, v.z, c.z);
        v.w = fmaf(a.w, v.w, c.w);
        if (relu) {
            v.x = fmaxf(v.x, 0.f); v.y = fmaxf(v.y, 0.f);
            v.z = fmaxf(v.z, 0.f); v.w = fmaxf(v.w, 0.f);
        }
    }
    float* p = g_z + (size_t)dst * DC + lane * 4;
    asm volatile("red.global.add.v4.f32 [%0], {%1, %2, %3, %4};"
                 :: "l"(p), "f"(v.x), "f"(v.y), "f"(v.z), "f"(v.w) : "memory");
}

// ---------------- fused GEMM + bias + BN-stats -------------------------------
// out[m][n] = sum_k f(A[m][k]) * W[k][n] + bias[n]
// f = identity (AFF=false) or relu(a[k]*x + c[k]) (AFF=true, BN1+ReLU fused load)
// also accumulates per-channel sum/sumsq of out into g_stats (valid rows only).
// Block: 256 threads, 128x128 tile, 8x8 per-thread register tile, K=128 in smem.
template<bool AFF>
__global__ void __launch_bounds__(256, 1)
k_gemm(const float* __restrict__ A, const float* __restrict__ W,
       const float* __restrict__ bias, float* __restrict__ out, int nrows)
{
    extern __shared__ float sm[];
    float* sA   = sm;                    // [128][132] (padded pitch)
    float* sB   = sm + 128 * 132;        // [128][128]
    float* sSum = sB + 128 * 128;        // [128]
    float* sSq  = sSum + DC;             // [128]

    const int t = threadIdx.x;
    const int blockRow = blockIdx.x * 128;

    // load W tile (whole 128x128)
    #pragma unroll
    for (int i = 0; i < 16; i++) {
        int idx = i * 256 + t;
        ((float4*)sB)[idx] = __ldg((const float4*)W + idx);
    }
    // load A tile with optional fused affine+relu; zero-pad invalid rows
    #pragma unroll
    for (int i = 0; i < 16; i++) {
        int idx = i * 256 + t;
        int m = idx >> 5;
        int k4 = idx & 31;
        int gm = blockRow + m;
        float4 v = make_float4(0.f, 0.f, 0.f, 0.f);
        if (gm < nrows) {
            v = __ldg((const float4*)(A + (size_t)gm * DC) + k4);
            if (AFF) {
                float4 a = *((const float4*)g_aff + k4);
                float4 c = *((const float4*)g_aff + DC / 4 + k4);
                v.x = fmaxf(fmaf(a.x, v.x, c.x), 0.f);
                v.y = fmaxf(fmaf(a.y, v.y, c.y), 0.f);
                v.z = fmaxf(fmaf(a.z, v.z, c.z), 0.f);
                v.w = fmaxf(fmaf(a.w, v.w, c.w), 0.f);
            }
        }
        *(float4*)(sA + m * 132 + k4 * 4) = v;
    }
    if (t < DC) { sSum[t] = 0.f; sSq[t] = 0.f; }
    __syncthreads();

    const int tx = t & 15, ty = t >> 4;
    const int m0 = ty * 8, n0 = tx * 8;

    float acc[8][8];
    #pragma unroll
    for (int i = 0; i < 8; i++)
        #pragma unroll
        for (int j = 0; j < 8; j++)
            acc[i][j] = 0.f;

    #pragma unroll 2
    for (int k0 = 0; k0 < DC; k0 += 4) {
        float4 av[8];
        #pragma unroll
        for (int i = 0; i < 8; i++)
            av[i] = *(const float4*)(sA + (m0 + i) * 132 + k0);
        #pragma unroll
        for (int kk = 0; kk < 4; kk++) {
            float4 b0 = *(const float4*)(sB + (k0 + kk) * DC + n0);
            float4 b1 = *(const float4*)(sB + (k0 + kk) * DC + n0 + 4);
            #pragma unroll
            for (int i = 0; i < 8; i++) {
                float a = (kk == 0) ? av[i].x : (kk == 1) ? av[i].y
                        : (kk == 2) ? av[i].z : av[i].w;
                acc[i][0] = fmaf(a, b0.x, acc[i][0]);
                acc[i][1] = fmaf(a, b0.y, acc[i][1]);
                acc[i][2] = fmaf(a, b0.z, acc[i][2]);
                acc[i][3] = fmaf(a, b0.w, acc[i][3]);
                acc[i][4] = fmaf(a, b1.x, acc[i][4]);
                acc[i][5] = fmaf(a, b1.y, acc[i][5]);
                acc[i][6] = fmaf(a, b1.z, acc[i][6]);
                acc[i][7] = fmaf(a, b1.w, acc[i][7]);
            }
        }
    }

    float4 bv0 = __ldg((const float4*)(bias + n0));
    float4 bv1 = __ldg((const float4*)(bias + n0) + 1);
    float csum[8] = {0, 0, 0, 0, 0, 0, 0, 0};
    float csq [8] = {0, 0, 0, 0, 0, 0, 0, 0};
    #pragma unroll
    for (int i = 0; i < 8; i++) {
        int gm = blockRow + m0 + i;
        float v0 = acc[i][0] + bv0.x, v1 = acc[i][1] + bv0.y;
        float v2 = acc[i][2] + bv0.z, v3 = acc[i][3] + bv0.w;
        float v4 = acc[i][4] + bv1.x, v5 = acc[i][5] + bv1.y;
        float v6 = acc[i][6] + bv1.z, v7 = acc[i][7] + bv1.w;
        if (gm < nrows) {
            float* po = out + (size_t)gm * DC + n0;
            *(float4*)po       = make_float4(v0, v1, v2, v3);
            *(float4*)(po + 4) = make_float4(v4, v5, v6, v7);
            csum[0] += v0; csq[0] += v0 * v0;
            csum[1] += v1; csq[1] += v1 * v1;
            csum[2] += v2; csq[2] += v2 * v2;
            csum[3] += v3; csq[3] += v3 * v3;
            csum[4] += v4; csq[4] += v4 * v4;
            csum[5] += v5; csq[5] += v5 * v5;
            csum[6] += v6; csq[6] += v6 * v6;
            csum[7] += v7; csq[7] += v7 * v7;
        }
    }
    #pragma unroll
    for (int j = 0; j < 8; j++) {
        atomicAdd(&sSum[n0 + j], csum[j]);
        atomicAdd(&sSq [n0 + j], csq [j]);
    }
    __syncthreads();
    if (t < DC) {
        atomicAdd(&g_stats[t],      sSum[t]);
        atomicAdd(&g_stats[DC + t], sSq[t]);
    }
}

// ---------------- BN stats -> per-channel affine; reset stats ---------------
__global__ void k_bn(const float* __restrict__ gamma, const float* __restrict__ beta)
{
    int c = threadIdx.x;
    float s  = g_stats[c];
    float sq = g_stats[DC + c];
    const float inv_n = 1.f / (float)NN;
    float mu  = s * inv_n;
    float var = fmaxf(sq * inv_n - mu * mu, 0.f);
    float a = __ldg(gamma + c) * rsqrtf(var + 1e-5f);
    g_aff[c]      = a;
    g_aff[DC + c] = __ldg(beta + c) - mu * a;
    g_stats[c]      = 0.f;   // leave zeroed for next GEMM / next graph replay
    g_stats[DC + c] = 0.f;
}

// ---------------- launcher ---------------------------------------------------
extern "C" void kernel_launch(void* const* d_in, const int* in_sizes, int n_in,
                              void* d_out, int out_size)
{
    const float* x   = (const float*)d_in[0];
    const int*   ei  = (const int*)  d_in[1];
    // d_in[2] edge_attr, d_in[3] batch: unused by the reference GINConv
    const float* W1  = (const float*)d_in[4];
    const float* b1  = (const float*)d_in[5];
    const float* g1  = (const float*)d_in[6];
    const float* be1 = (const float*)d_in[7];
    const float* W2  = (const float*)d_in[8];
    const float* b2  = (const float*)d_in[9];
    const float* g2  = (const float*)d_in[10];
    const float* be2 = (const float*)d_in[11];
    float* out = (float*)d_out;

    float *zp, *t1p, *t2p;
    cudaGetSymbolAddress((void**)&zp,  g_z);
    cudaGetSymbolAddress((void**)&t1p, g_t1);
    cudaGetSymbolAddress((void**)&t2p, g_t2);

    const size_t SMEM = (size_t)(128 * 132 + 128 * 128 + 2 * DC) * sizeof(float);
    cudaFuncSetAttribute(k_gemm<false>, cudaFuncAttributeMaxDynamicSharedMemorySize, (int)SMEM);
    cudaFuncSetAttribute(k_gemm<true>,  cudaFuncAttributeMaxDynamicSharedMemorySize, (int)SMEM);

    const int AFF_BLOCKS  = (NN * DC / 4 + 255) / 256;
    const int SC_BLOCKS   = (NE * 32 + 255) / 256;
    const int GEMM_BLOCKS = (NN + 127) / 128;

    k_zero_stats<<<1, 256>>>();

    const float* h = x;
    for (int l = 0; l < NL; l++) {
        if (l == 0) {
            // z = h + sum_j h[src]
            k_affine<false><<<AFF_BLOCKS, 256>>>(h, zp, 0);
            k_scatter<false><<<SC_BLOCKS, 256>>>(h, ei, 0);
        } else {
            // previous layer's BN2(+ReLU) fused into the aggregation reads
            k_affine<true><<<AFF_BLOCKS, 256>>>(h, zp, 1);
            k_scatter<true><<<SC_BLOCKS, 256>>>(h, ei, 1);
        }
        // t1 = z @ W1 + b1   (+ BN1 stats)
        k_gemm<false><<<GEMM_BLOCKS, 256, SMEM>>>(zp, W1 + l * DC * DC, b1 + l * DC, t1p, NN);
        k_bn<<<1, DC>>>(g1 + l * DC, be1 + l * DC);
        // t2 = relu(BN1(t1)) @ W2 + b2   (+ BN2 stats; BN1+ReLU fused into A load)
        k_gemm<true><<<GEMM_BLOCKS, 256, SMEM>>>(t1p, W2 + l * DC * DC, b2 + l * DC, t2p, NN);
        k_bn<<<1, DC>>>(g2 + l * DC, be2 + l * DC);
        h = t2p;
    }
    // final: out = BN2(t2) of last layer, no ReLU
    k_affine<true><<<AFF_BLOCKS, 256>>>(t2p, out, 0);
}